// round 3
// baseline (speedup 1.0000x reference)
#include <cuda_runtime.h>
#include <cuda_fp16.h>
#include <cstdint>

#define EPSF 1e-5f
#define MAX_N 524288  // capacity for rows of h (N = 500000 here)

// Scratch (allocation-free): fp16 shadow of h (64 MB) + accumulators.
__device__ __half2 g_h16[MAX_N * 32];   // 32 half2 per 64-dim row
__device__ double  g_acc[3];            // [0]=sum sp(pos), [1]=sum sp(-neg), [2]=sum 1/(rank+1)

__global__ void hat_init_acc() {
    if (threadIdx.x < 3) g_acc[threadIdx.x] = 0.0;
}

// fp32 -> fp16 shadow copy. One float4 (16B) in -> one uint2 (8B, 4 halves) out.
__global__ void hat_convert_kernel(const float* __restrict__ h, int total4) {
    int i = blockIdx.x * blockDim.x + threadIdx.x;
    if (i >= total4) return;
    float4 v = reinterpret_cast<const float4*>(h)[i];
    __half2 a = __floats2half2_rn(v.x, v.y);
    __half2 b = __floats2half2_rn(v.z, v.w);
    uint2 packed;
    packed.x = *reinterpret_cast<unsigned*>(&a);
    packed.y = *reinterpret_cast<unsigned*>(&b);
    reinterpret_cast<uint2*>(g_h16)[i] = packed;
}

__device__ __forceinline__ float softplusf(float x) {
    return fmaxf(x, 0.0f) + log1pf(__expf(-fabsf(x)));
}

// Warp per pos-edge group (1 pos + neg_nums negs). Persistent grid-stride.
// Rows gathered from the fp16 shadow (128B coalesced per row); norms reduced
// in the same shuffle pass so no alpha table / gather is needed.
__global__ void __launch_bounds__(256) hat_main_kernel(
    const int* __restrict__ pos_src, const int* __restrict__ pos_dst,
    const int* __restrict__ neg_src, const int* __restrict__ neg_dst,
    int E_pos, int neg_nums)
{
    const int lane        = threadIdx.x & 31;
    const int warp_global = (blockIdx.x * blockDim.x + threadIdx.x) >> 5;
    const int nwarps      = (gridDim.x * blockDim.x) >> 5;

    float acc_pos = 0.0f;   // lane 0
    float acc_neg = 0.0f;   // lanes 1..neg_nums
    float acc_mrr = 0.0f;   // lane 0

    for (int i = warp_global; i < E_pos; i += nwarps) {
        // Lane e in [0, neg_nums] owns edge e: lane 0 = positive, 1..neg_nums = negatives.
        int s_idx = 0, d_idx = 0;
        if (lane == 0)             { s_idx = pos_src[i];  d_idx = pos_dst[i]; }
        else if (lane <= neg_nums) { int b = i * neg_nums + lane - 1;
                                     s_idx = neg_src[b];  d_idx = neg_dst[b]; }

        float my_sq = 0.0f, my_ab = 1.0f;
        #pragma unroll 6
        for (int e = 0; e <= neg_nums; e++) {
            int s = __shfl_sync(0xFFFFFFFFu, s_idx, e);
            int d = __shfl_sync(0xFFFFFFFFu, d_idx, e);
            __half2 uh = g_h16[(s << 5) + lane];
            __half2 vh = g_h16[(d << 5) + lane];
            float2 u = __half22float2(uh);
            float2 v = __half22float2(vh);
            float dx = u.x - v.x, dy = u.y - v.y;
            float sq = fmaf(dx, dx, dy * dy);
            float uu = fmaf(u.x, u.x, u.y * u.y);
            float vv = fmaf(v.x, v.x, v.y * v.y);
            #pragma unroll
            for (int o = 16; o; o >>= 1) {
                sq += __shfl_xor_sync(0xFFFFFFFFu, sq, o);
                uu += __shfl_xor_sync(0xFFFFFFFFu, uu, o);
                vv += __shfl_xor_sync(0xFFFFFFFFu, vv, o);
            }
            if (lane == e) {
                my_sq = sq;
                my_ab = fmaxf(1.0f - uu, EPSF) * fmaxf(1.0f - vv, EPSF);
            }
        }

        // Lanes 0..neg_nums compute their Poincare dist^2 in parallel.
        float score = 0.0f;
        if (lane <= neg_nums) {
            float x = fmaxf(2.0f * my_sq / my_ab, EPSF);           // gamma - 1
            float dd = log1pf(x + sqrtf(x * (x + 2.0f)));          // arccosh(1+x)
            score = dd * dd;
        }
        float pos_score = __shfl_sync(0xFFFFFFFFu, score, 0);

        // rank = #{neg: neg_score < pos_score}  (strict, matches logits >)
        unsigned lt = __ballot_sync(0xFFFFFFFFu,
                                    (lane >= 1) && (lane <= neg_nums) && (score < pos_score));
        int rank = __popc(lt);

        if (lane == 0) {
            acc_pos += softplusf(score);
            acc_mrr += 1.0f / (float)(rank + 1);
        } else if (lane <= neg_nums) {
            acc_neg += softplusf(-score);
        }
    }

    #pragma unroll
    for (int o = 16; o; o >>= 1) acc_neg += __shfl_xor_sync(0xFFFFFFFFu, acc_neg, o);

    __shared__ float s_pos[8], s_neg[8], s_mrr[8];
    int wid = threadIdx.x >> 5;
    if (lane == 0) { s_pos[wid] = acc_pos; s_neg[wid] = acc_neg; s_mrr[wid] = acc_mrr; }
    __syncthreads();
    if (threadIdx.x == 0) {
        double p = 0.0, n = 0.0, m = 0.0;
        int nw = blockDim.x >> 5;
        for (int w = 0; w < nw; w++) { p += s_pos[w]; n += s_neg[w]; m += s_mrr[w]; }
        atomicAdd(&g_acc[0], p);
        atomicAdd(&g_acc[1], n);
        atomicAdd(&g_acc[2], m);
    }
}

__global__ void hat_finalize(float* __restrict__ out, int E_pos, int E_neg, int out_size) {
    if (threadIdx.x == 0 && blockIdx.x == 0) {
        float loss = (float)(g_acc[0] / (double)E_pos + g_acc[1] / (double)E_neg);
        float mrr  = (float)(g_acc[2] / (double)E_pos);
        out[0] = loss;
        if (out_size > 1) out[1] = mrr;
    }
}

extern "C" void kernel_launch(void* const* d_in, const int* in_sizes, int n_in,
                              void* d_out, int out_size)
{
    const float* h       = (const float*)d_in[0];
    const int*   pos_src = (const int*)d_in[1];
    const int*   pos_dst = (const int*)d_in[2];
    const int*   neg_src = (const int*)d_in[3];
    const int*   neg_dst = (const int*)d_in[4];

    int h_elems = in_sizes[0];
    int E_pos   = in_sizes[1];
    int E_neg   = in_sizes[3];
    int neg_nums = (E_pos > 0) ? (E_neg / E_pos) : 1;

    float* out = (float*)d_out;

    hat_init_acc<<<1, 32>>>();

    // fp32 -> fp16 shadow table
    {
        int total4  = h_elems / 4;
        int threads = 256;
        int blocks  = (total4 + threads - 1) / threads;
        hat_convert_kernel<<<blocks, threads>>>(h, total4);
    }

    // main: persistent grid-stride, warp per edge-group
    {
        int threads = 256;
        int blocks  = 148 * 8;
        hat_main_kernel<<<blocks, threads>>>(pos_src, pos_dst, neg_src, neg_dst,
                                             E_pos, neg_nums);
    }

    hat_finalize<<<1, 32>>>(out, E_pos, E_neg, out_size);
}

// round 4
// speedup vs baseline: 1.3617x; 1.3617x over previous
#include <cuda_runtime.h>
#include <cuda_fp16.h>
#include <cstdint>

#define EPSF 1e-5f
#define MAX_N 524288  // capacity for rows of h (N = 500000 here)

// Scratch (allocation-free): fp16 shadow of h (64 MB), fp32 alpha table, accumulators.
__device__ __half2 g_h16[MAX_N * 32];   // 32 half2 per 64-dim row (128 B/row)
__device__ float   g_alpha[MAX_N];      // max(1 - ||h_i||^2, EPS), computed in fp32
__device__ double  g_acc[3];            // [0]=sum sp(pos), [1]=sum sp(-neg), [2]=sum 1/(rank+1)

__global__ void hat_init_acc() {
    if (threadIdx.x < 3) g_acc[threadIdx.x] = 0.0;
}

// Fused fp32->fp16 convert + alpha. Each thread handles one float4 (4 dims);
// 16 consecutive threads cover one 64-dim row; segmented shuffle reduce for the norm.
__global__ void hat_convert_kernel(const float* __restrict__ h, int total4) {
    int i = blockIdx.x * blockDim.x + threadIdx.x;
    bool ok = (i < total4);
    float4 v = make_float4(0.f, 0.f, 0.f, 0.f);
    if (ok) v = reinterpret_cast<const float4*>(h)[i];

    if (ok) {
        __half2 a = __floats2half2_rn(v.x, v.y);
        __half2 b = __floats2half2_rn(v.z, v.w);
        uint2 packed;
        packed.x = *reinterpret_cast<unsigned*>(&a);
        packed.y = *reinterpret_cast<unsigned*>(&b);
        reinterpret_cast<uint2*>(g_h16)[i] = packed;
    }

    // norm^2 partial over this thread's 4 dims, reduced across the 16-lane segment
    float s = fmaf(v.x, v.x, fmaf(v.y, v.y, fmaf(v.z, v.z, v.w * v.w)));
    #pragma unroll
    for (int o = 8; o; o >>= 1) s += __shfl_xor_sync(0xFFFFFFFFu, s, o);
    if (ok && ((threadIdx.x & 15) == 0)) g_alpha[i >> 4] = fmaxf(1.0f - s, EPSF);
}

__device__ __forceinline__ float softplusf(float x) {
    return fmaxf(x, 0.0f) + log1pf(__expf(-fabsf(x)));
}

// Warp per pos-edge group (1 pos + NEG negs), fully unrolled. All 2*(NEG+1) row
// loads issued up-front for MLP; only sq is shuffle-reduced (5 stages, 6-way ILP).
template<int NEG>
__global__ void __launch_bounds__(256) hat_main_t(
    const int* __restrict__ pos_src, const int* __restrict__ pos_dst,
    const int* __restrict__ neg_src, const int* __restrict__ neg_dst,
    int E_pos)
{
    constexpr int E = NEG + 1;
    const int lane        = threadIdx.x & 31;
    const int warp_global = (blockIdx.x * blockDim.x + threadIdx.x) >> 5;
    const int nwarps      = (gridDim.x * blockDim.x) >> 5;

    float acc_pos = 0.0f, acc_neg = 0.0f, acc_mrr = 0.0f;

    for (int i = warp_global; i < E_pos; i += nwarps) {
        // Lane e in [0, NEG] owns edge e: lane 0 = positive, 1..NEG = negatives.
        int s_idx = 0, d_idx = 0;
        if (lane == 0)        { s_idx = pos_src[i];  d_idx = pos_dst[i]; }
        else if (lane <= NEG) { int b = i * NEG + lane - 1;
                                s_idx = neg_src[b];  d_idx = neg_dst[b]; }

        float my_ab = 1.0f;
        if (lane <= NEG) my_ab = g_alpha[s_idx] * g_alpha[d_idx];

        // Batch all row loads (12 half2 loads in flight)
        __half2 uh[E], vh[E];
        #pragma unroll
        for (int e = 0; e < E; e++) {
            int s = __shfl_sync(0xFFFFFFFFu, s_idx, e);
            int d = __shfl_sync(0xFFFFFFFFu, d_idx, e);
            uh[e] = g_h16[(s << 5) + lane];
            vh[e] = g_h16[(d << 5) + lane];
        }

        float sqv[E];
        #pragma unroll
        for (int e = 0; e < E; e++) {
            float2 u = __half22float2(uh[e]);
            float2 v = __half22float2(vh[e]);
            float dx = u.x - v.x, dy = u.y - v.y;
            sqv[e] = fmaf(dx, dx, dy * dy);
        }
        // Interleaved butterfly reduce: 5 stages x E independent shfls
        #pragma unroll
        for (int o = 16; o; o >>= 1) {
            #pragma unroll
            for (int e = 0; e < E; e++)
                sqv[e] += __shfl_xor_sync(0xFFFFFFFFu, sqv[e], o);
        }
        float my_sq = 0.0f;
        #pragma unroll
        for (int e = 0; e < E; e++) if (lane == e) my_sq = sqv[e];

        // Lanes 0..NEG compute their Poincare dist^2 in parallel.
        float score = 0.0f;
        if (lane <= NEG) {
            float x = fmaxf(2.0f * my_sq / my_ab, EPSF);           // gamma - 1
            float dd = log1pf(x + sqrtf(x * (x + 2.0f)));          // arccosh(1+x)
            score = dd * dd;
        }
        float pos_score = __shfl_sync(0xFFFFFFFFu, score, 0);

        unsigned lt = __ballot_sync(0xFFFFFFFFu,
                                    (lane >= 1) && (lane <= NEG) && (score < pos_score));
        int rank = __popc(lt);

        if (lane == 0) {
            acc_pos += softplusf(score);
            acc_mrr += 1.0f / (float)(rank + 1);
        } else if (lane <= NEG) {
            acc_neg += softplusf(-score);
        }
    }

    #pragma unroll
    for (int o = 16; o; o >>= 1) acc_neg += __shfl_xor_sync(0xFFFFFFFFu, acc_neg, o);

    __shared__ float s_pos[8], s_neg[8], s_mrr[8];
    int wid = threadIdx.x >> 5;
    if (lane == 0) { s_pos[wid] = acc_pos; s_neg[wid] = acc_neg; s_mrr[wid] = acc_mrr; }
    __syncthreads();
    if (threadIdx.x == 0) {
        double p = 0.0, n = 0.0, m = 0.0;
        int nw = blockDim.x >> 5;
        for (int w = 0; w < nw; w++) { p += s_pos[w]; n += s_neg[w]; m += s_mrr[w]; }
        atomicAdd(&g_acc[0], p);
        atomicAdd(&g_acc[1], n);
        atomicAdd(&g_acc[2], m);
    }
}

// Generic fallback for unexpected neg_nums (same structure, runtime loop).
__global__ void __launch_bounds__(256) hat_main_generic(
    const int* __restrict__ pos_src, const int* __restrict__ pos_dst,
    const int* __restrict__ neg_src, const int* __restrict__ neg_dst,
    int E_pos, int neg_nums)
{
    const int lane        = threadIdx.x & 31;
    const int warp_global = (blockIdx.x * blockDim.x + threadIdx.x) >> 5;
    const int nwarps      = (gridDim.x * blockDim.x) >> 5;

    float acc_pos = 0.0f, acc_neg = 0.0f, acc_mrr = 0.0f;

    for (int i = warp_global; i < E_pos; i += nwarps) {
        int s_idx = 0, d_idx = 0;
        if (lane == 0)             { s_idx = pos_src[i];  d_idx = pos_dst[i]; }
        else if (lane <= neg_nums) { int b = i * neg_nums + lane - 1;
                                     s_idx = neg_src[b];  d_idx = neg_dst[b]; }
        float my_ab = 1.0f;
        if (lane <= neg_nums) my_ab = g_alpha[s_idx] * g_alpha[d_idx];

        float my_sq = 0.0f;
        for (int e = 0; e <= neg_nums; e++) {
            int s = __shfl_sync(0xFFFFFFFFu, s_idx, e);
            int d = __shfl_sync(0xFFFFFFFFu, d_idx, e);
            float2 u = __half22float2(g_h16[(s << 5) + lane]);
            float2 v = __half22float2(g_h16[(d << 5) + lane]);
            float dx = u.x - v.x, dy = u.y - v.y;
            float sq = fmaf(dx, dx, dy * dy);
            #pragma unroll
            for (int o = 16; o; o >>= 1) sq += __shfl_xor_sync(0xFFFFFFFFu, sq, o);
            if (lane == e) my_sq = sq;
        }

        float score = 0.0f;
        if (lane <= neg_nums) {
            float x = fmaxf(2.0f * my_sq / my_ab, EPSF);
            float dd = log1pf(x + sqrtf(x * (x + 2.0f)));
            score = dd * dd;
        }
        float pos_score = __shfl_sync(0xFFFFFFFFu, score, 0);
        unsigned lt = __ballot_sync(0xFFFFFFFFu,
                                    (lane >= 1) && (lane <= neg_nums) && (score < pos_score));
        int rank = __popc(lt);

        if (lane == 0) { acc_pos += softplusf(score); acc_mrr += 1.0f / (float)(rank + 1); }
        else if (lane <= neg_nums) acc_neg += softplusf(-score);
    }

    #pragma unroll
    for (int o = 16; o; o >>= 1) acc_neg += __shfl_xor_sync(0xFFFFFFFFu, acc_neg, o);

    __shared__ float s_pos[8], s_neg[8], s_mrr[8];
    int wid = threadIdx.x >> 5;
    if (lane == 0) { s_pos[wid] = acc_pos; s_neg[wid] = acc_neg; s_mrr[wid] = acc_mrr; }
    __syncthreads();
    if (threadIdx.x == 0) {
        double p = 0.0, n = 0.0, m = 0.0;
        int nw = blockDim.x >> 5;
        for (int w = 0; w < nw; w++) { p += s_pos[w]; n += s_neg[w]; m += s_mrr[w]; }
        atomicAdd(&g_acc[0], p);
        atomicAdd(&g_acc[1], n);
        atomicAdd(&g_acc[2], m);
    }
}

__global__ void hat_finalize(float* __restrict__ out, int E_pos, int E_neg, int out_size) {
    if (threadIdx.x == 0 && blockIdx.x == 0) {
        float loss = (float)(g_acc[0] / (double)E_pos + g_acc[1] / (double)E_neg);
        float mrr  = (float)(g_acc[2] / (double)E_pos);
        out[0] = loss;
        if (out_size > 1) out[1] = mrr;
    }
}

extern "C" void kernel_launch(void* const* d_in, const int* in_sizes, int n_in,
                              void* d_out, int out_size)
{
    const float* h       = (const float*)d_in[0];
    const int*   pos_src = (const int*)d_in[1];
    const int*   pos_dst = (const int*)d_in[2];
    const int*   neg_src = (const int*)d_in[3];
    const int*   neg_dst = (const int*)d_in[4];

    int h_elems  = in_sizes[0];
    int E_pos    = in_sizes[1];
    int E_neg    = in_sizes[3];
    int neg_nums = (E_pos > 0) ? (E_neg / E_pos) : 1;

    float* out = (float*)d_out;

    hat_init_acc<<<1, 32>>>();

    // fused fp32->fp16 shadow + alpha table
    {
        int total4  = h_elems / 4;
        int threads = 256;
        int blocks  = (total4 + threads - 1) / threads;
        hat_convert_kernel<<<blocks, threads>>>(h, total4);
    }

    // main: persistent grid-stride, warp per edge-group
    {
        int threads = 256;
        int blocks  = 148 * 8;
        if (neg_nums == 5)
            hat_main_t<5><<<blocks, threads>>>(pos_src, pos_dst, neg_src, neg_dst, E_pos);
        else
            hat_main_generic<<<blocks, threads>>>(pos_src, pos_dst, neg_src, neg_dst,
                                                  E_pos, neg_nums);
    }

    hat_finalize<<<1, 32>>>(out, E_pos, E_neg, out_size);
}